// round 8
// baseline (speedup 1.0000x reference)
#include <cuda_runtime.h>
#include <cuda_bf16.h>
#include <cuda_fp16.h>
#include <math.h>
#include <stdint.h>

#define B_    16
#define C_    256
#define N_    4096
#define HEADS 8
#define DH    32
#define QKV3  768
#define LN_EPS 1e-5f
#define L2_EPS 1e-12f
#define XC_SCALE 8.0f
#define ZSPLIT 8

// ---------------- scratch ----------------
__device__ __nv_bfloat16 g_thi[(size_t)B_ * N_ * C_];
__device__ __nv_bfloat16 g_tlo[(size_t)B_ * N_ * C_];
__device__ __half g_qkvh[(size_t)B_ * QKV3 * N_];         // q,k,v fp16  [b][j][n]
__device__ float g_norm2[B_ * 512];                       // q(0..255), k(256..511) sumsq
__device__ float g_simpart[ZSPLIT * B_ * HEADS * DH * DH];
__device__ float g_attn[B_ * HEADS * DH * DH];
__device__ __nv_bfloat16 g_avhi[(size_t)B_ * N_ * C_];
__device__ __nv_bfloat16 g_avlo[(size_t)B_ * N_ * C_];
__device__ __nv_bfloat16 g_wqh[QKV3 * C_];
__device__ __nv_bfloat16 g_wql[QKV3 * C_];
__device__ __nv_bfloat16 g_woh[C_ * C_];
__device__ __nv_bfloat16 g_wol[C_ * C_];

__device__ __forceinline__ uint32_t smem_u32(const void* p) {
    uint32_t a;
    asm("{ .reg .u64 t; cvta.to.shared.u64 t, %1; cvt.u32.u64 %0, t; }" : "=r"(a) : "l"(p));
    return a;
}
__device__ __forceinline__ void mma_bf16(float* c, const uint32_t* a, const uint32_t* b) {
    asm volatile("mma.sync.aligned.m16n8k16.row.col.f32.bf16.bf16.f32 "
                 "{%0,%1,%2,%3}, {%4,%5,%6,%7}, {%8,%9}, {%0,%1,%2,%3};"
                 : "+f"(c[0]), "+f"(c[1]), "+f"(c[2]), "+f"(c[3])
                 : "r"(a[0]), "r"(a[1]), "r"(a[2]), "r"(a[3]), "r"(b[0]), "r"(b[1]));
}
__device__ __forceinline__ void ldsm4(uint32_t* r, uint32_t addr) {
    asm volatile("ldmatrix.sync.aligned.m8n8.x4.shared.b16 {%0,%1,%2,%3}, [%4];"
                 : "=r"(r[0]), "=r"(r[1]), "=r"(r[2]), "=r"(r[3]) : "r"(addr));
}
__device__ __forceinline__ void cp16(uint32_t sa, const void* ga) {
    asm volatile("cp.async.cg.shared.global [%0], [%1], 16;" :: "r"(sa), "l"(ga) : "memory");
}
#define CP_COMMIT() asm volatile("cp.async.commit_group;" ::: "memory")
#define CP_WAIT1()  asm volatile("cp.async.wait_group 1;" ::: "memory")
#define CP_WAIT0()  asm volatile("cp.async.wait_group 0;" ::: "memory")

// ---------------- Kernel 0: zero norm accumulators ----------------
__global__ void zero_kernel() {
    int i = blockIdx.x * 256 + threadIdx.x;
    if (i < B_ * 512) g_norm2[i] = 0.f;
}

// ---------------- Kernel 1: fused LayerNorm + transpose + bf16 split ----------------
__global__ __launch_bounds__(256) void lnconv_kernel(const float* __restrict__ x,
                                                     const float* __restrict__ gamma,
                                                     const float* __restrict__ beta) {
    __shared__ float s[256][33];
    __shared__ float p1[8][32], p2[8][32];
    __shared__ float mu_s[32], rs_s[32];
    int tid = threadIdx.x;
    int b = blockIdx.y, n0 = blockIdx.x * 32;
    int nl = tid & 31, g = tid >> 5;

    float a1 = 0.f, a2 = 0.f;
    for (int c = g; c < 256; c += 8) {
        float v = x[((size_t)b * 256 + c) * 4096 + n0 + nl];
        s[c][nl] = v;
        a1 += v; a2 += v * v;
    }
    p1[g][nl] = a1; p2[g][nl] = a2;
    __syncthreads();
    if (tid < 32) {
        float s1 = 0.f, s2 = 0.f;
        #pragma unroll
        for (int gg = 0; gg < 8; gg++) { s1 += p1[gg][tid]; s2 += p2[gg][tid]; }
        float mu = s1 * (1.0f / 256.0f);
        float var = s2 * (1.0f / 256.0f) - mu * mu;
        mu_s[tid] = mu;
        rs_s[tid] = rsqrtf(var + LN_EPS);
    }
    __syncthreads();

    float gm = gamma[tid], bt = beta[tid];
    #pragma unroll 4
    for (int n = 0; n < 32; n++) {
        float v = (s[tid][n] - mu_s[n]) * rs_s[n] * gm + bt;
        __nv_bfloat16 h = __float2bfloat16(v);
        __nv_bfloat16 l = __float2bfloat16(v - __bfloat162float(h));
        size_t o = ((size_t)b * 4096 + n0 + n) * 256 + tid;
        g_thi[o] = h;
        g_tlo[o] = l;
    }
}

// ---------------- Kernel 2: weight transpose + split (both weights, one launch) ----------------
__global__ void wsplit_kernel(const float* __restrict__ Wq, const float* __restrict__ Wo) {
    __shared__ float tb[32][33];
    int bid = blockIdx.x;
    const float* W;
    __nv_bfloat16 *hi, *lo;
    int M, m0, k0;
    if (bid < 192) {                    // Wqkv: 24 x 8 tiles
        W = Wq; hi = g_wqh; lo = g_wql; M = QKV3;
        m0 = (bid % 24) * 32; k0 = (bid / 24) * 32;
    } else {                            // Wout: 8 x 8 tiles
        bid -= 192;
        W = Wo; hi = g_woh; lo = g_wol; M = C_;
        m0 = (bid % 8) * 32; k0 = (bid / 8) * 32;
    }
    int tx = threadIdx.x, ty = threadIdx.y;
    for (int r = ty; r < 32; r += 8)
        tb[r][tx] = W[(size_t)(k0 + r) * M + m0 + tx];
    __syncthreads();
    for (int r = ty; r < 32; r += 8) {
        float v = tb[tx][r];
        __nv_bfloat16 h = __float2bfloat16(v);
        __nv_bfloat16 l = __float2bfloat16(v - __bfloat162float(h));
        size_t o = (size_t)(m0 + r) * 256 + k0 + tx;
        hi[o] = h; lo[o] = l;
    }
}

// ---------------- Kernel 3: pipelined ldmatrix split-bf16 HMMA GEMM ----------------
// mode 0: A=g_thi/lo, B=g_wqh/l -> g_qkvh (fp16) + fused q/k norms
// mode 1: A=g_avhi/lo, B=g_woh/l -> out_ext fp32 (+bias)
#define STG 32768

__global__ __launch_bounds__(256) void mgemm_kernel(int mode, float* __restrict__ out_ext,
                                                    const float* __restrict__ bias, int Mtotal) {
    extern __shared__ char sm[];
    uint32_t smb = smem_u32(sm);

    int tid = threadIdx.x, wid = tid >> 5, lane = tid & 31;
    int qrow = lane >> 2, qcol = lane & 3;
    int warp_m = wid >> 2;
    int warp_n = wid & 3;
    int n0 = blockIdx.x * 128, j0 = blockIdx.y * 128, b = blockIdx.z;

    const uint4* Agh = (const uint4*)(mode == 0 ? g_thi : g_avhi);
    const uint4* Agl = (const uint4*)(mode == 0 ? g_tlo : g_avlo);
    const uint4* Bgh = (const uint4*)(mode == 0 ? g_wqh : g_woh);
    const uint4* Bgl = (const uint4*)(mode == 0 ? g_wql : g_wol);

    int lr0 = tid >> 2;
    int lc = tid & 3;
    uint32_t so0 = (uint32_t)(lr0 * 64 + ((lc ^ ((lr0 >> 1) & 3)) * 16));
    int lr1 = lr0 + 64;
    uint32_t so1 = (uint32_t)(lr1 * 64 + ((lc ^ ((lr1 >> 1) & 3)) * 16));

    float acc[4][4][4] = {};

    {
        size_t ga0 = ((size_t)(b * 4096 + n0 + lr0)) * 32 + lc;
        size_t ga1 = ((size_t)(b * 4096 + n0 + lr1)) * 32 + lc;
        size_t gb0 = ((size_t)(j0 + lr0)) * 32 + lc;
        size_t gb1 = ((size_t)(j0 + lr1)) * 32 + lc;
        cp16(smb + so0,         Agh + ga0);
        cp16(smb + so1,         Agh + ga1);
        cp16(smb + 8192 + so0,  Agl + ga0);
        cp16(smb + 8192 + so1,  Agl + ga1);
        cp16(smb + 16384 + so0, Bgh + gb0);
        cp16(smb + 16384 + so1, Bgh + gb1);
        cp16(smb + 24576 + so0, Bgl + gb0);
        cp16(smb + 24576 + so1, Bgl + gb1);
        CP_COMMIT();
    }

    int aRow = (lane & 15);
    int aCol = lane >> 4;
    int bRow = ((lane >> 4) << 3) + (lane & 7);
    int bCol = (lane >> 3) & 1;

    for (int chunk = 0; chunk < 8; chunk++) {
        if (chunk < 7) {
            int k8 = (chunk + 1) * 4;
            uint32_t st = smb + ((chunk + 1) & 1) * STG;
            size_t ga0 = ((size_t)(b * 4096 + n0 + lr0)) * 32 + k8 + lc;
            size_t ga1 = ((size_t)(b * 4096 + n0 + lr1)) * 32 + k8 + lc;
            size_t gb0 = ((size_t)(j0 + lr0)) * 32 + k8 + lc;
            size_t gb1 = ((size_t)(j0 + lr1)) * 32 + k8 + lc;
            cp16(st + so0,          Agh + ga0);
            cp16(st + so1,          Agh + ga1);
            cp16(st + 8192 + so0,   Agl + ga0);
            cp16(st + 8192 + so1,   Agl + ga1);
            cp16(st + 16384 + so0,  Bgh + gb0);
            cp16(st + 16384 + so1,  Bgh + gb1);
            cp16(st + 24576 + so0,  Bgl + gb0);
            cp16(st + 24576 + so1,  Bgl + gb1);
            CP_COMMIT();
            CP_WAIT1();
        } else {
            CP_WAIT0();
        }
        __syncthreads();

        uint32_t st = smb + (chunk & 1) * STG;
        #pragma unroll
        for (int kk = 0; kk < 2; kk++) {
            uint32_t bh[2][4], bl[2][4];
            #pragma unroll
            for (int np = 0; np < 2; np++) {
                int row = warp_n * 32 + np * 16 + bRow;
                uint32_t cc = (uint32_t)(((kk * 2) | bCol) ^ ((row >> 1) & 3));
                uint32_t ad = st + 16384 + (uint32_t)(row * 64) + cc * 16;
                ldsm4(bh[np], ad);
                ldsm4(bl[np], ad + 8192);
            }
            #pragma unroll
            for (int mf = 0; mf < 4; mf++) {
                int row = warp_m * 64 + mf * 16 + aRow;
                uint32_t cc = (uint32_t)(((kk * 2) | aCol) ^ ((row >> 1) & 3));
                uint32_t ad = st + (uint32_t)(row * 64) + cc * 16;
                uint32_t ah[4], al[4];
                ldsm4(ah, ad);
                ldsm4(al, ad + 8192);
                #pragma unroll
                for (int nf = 0; nf < 4; nf++) {
                    const uint32_t* bhf = &bh[nf >> 1][(nf & 1) * 2];
                    const uint32_t* blf = &bl[nf >> 1][(nf & 1) * 2];
                    mma_bf16(acc[mf][nf], ah, bhf);
                    mma_bf16(acc[mf][nf], ah, blf);
                    mma_bf16(acc[mf][nf], al, bhf);
                }
            }
        }
        __syncthreads();
    }

    if (mode == 0) {
        // fp16 stores to g_qkvh
        __half* Ch = g_qkvh + (size_t)b * QKV3 * N_;
        #pragma unroll
        for (int mf = 0; mf < 4; mf++) {
            int m = n0 + warp_m * 64 + mf * 16 + qrow;
            #pragma unroll
            for (int nf = 0; nf < 4; nf++) {
                int j = j0 + warp_n * 32 + nf * 8 + qcol * 2;
                size_t r0 = (size_t)j * N_ + m;
                size_t r1 = r0 + N_;
                Ch[r0]     = __float2half(acc[mf][nf][0]);
                Ch[r1]     = __float2half(acc[mf][nf][1]);
                Ch[r0 + 8] = __float2half(acc[mf][nf][2]);
                Ch[r1 + 8] = __float2half(acc[mf][nf][3]);
            }
        }
        // fused q/k L2-norm partials (register path)
        if (blockIdx.y < 4) {
            #pragma unroll
            for (int nf = 0; nf < 4; nf++) {
                float s0 = 0.f, s1 = 0.f;
                #pragma unroll
                for (int mf = 0; mf < 4; mf++) {
                    s0 += acc[mf][nf][0] * acc[mf][nf][0] + acc[mf][nf][2] * acc[mf][nf][2];
                    s1 += acc[mf][nf][1] * acc[mf][nf][1] + acc[mf][nf][3] * acc[mf][nf][3];
                }
                #pragma unroll
                for (int o = 16; o >= 4; o >>= 1) {
                    s0 += __shfl_down_sync(0xffffffffu, s0, o);
                    s1 += __shfl_down_sync(0xffffffffu, s1, o);
                }
                if (qrow == 0) {
                    int j = j0 + warp_n * 32 + nf * 8 + qcol * 2;
                    atomicAdd(&g_norm2[b * 512 + j], s0);
                    atomicAdd(&g_norm2[b * 512 + j + 1], s1);
                }
            }
        }
    } else {
        #pragma unroll
        for (int mf = 0; mf < 4; mf++) {
            int m = n0 + warp_m * 64 + mf * 16 + qrow;
            #pragma unroll
            for (int nf = 0; nf < 4; nf++) {
                int j = j0 + warp_n * 32 + nf * 8 + qcol * 2;
                float b0 = bias[j], b1 = bias[j + 1];
                size_t r0 = ((size_t)b * Mtotal + j) * N_ + m;
                size_t r1 = r0 + N_;
                out_ext[r0]     = acc[mf][nf][0] + b0;
                out_ext[r1]     = acc[mf][nf][1] + b1;
                out_ext[r0 + 8] = acc[mf][nf][2] + b0;
                out_ext[r1 + 8] = acc[mf][nf][3] + b1;
            }
        }
    }
}

// ---------------- Kernel 5: sim partials (split-K x ZSPLIT, fp16 inputs) ----------------
#define CHN 128
#define PAD 132
__global__ void sim_part_kernel() {
    __shared__ float qs[32 * PAD];
    __shared__ float ks[32 * PAD];
    __shared__ float simbuf[32 * 32];

    int bh = blockIdx.x, z = blockIdx.y;
    int b = bh >> 3, h = bh & 7;
    int tid = threadIdx.x;
    const __half* qbase = g_qkvh + ((size_t)b * QKV3 + h * DH) * N_;
    const __half* kbase = g_qkvh + ((size_t)b * QKV3 + 256 + h * DH) * N_;

    for (int l = tid; l < 1024; l += 256) simbuf[l] = 0.f;

    int g = tid >> 6;
    int p = tid & 63;
    int ii0 = (p >> 3) * 4;
    int jj0 = (p & 7) * 4;
    float acc[4][4] = {};

    int nstart = z * (N_ / ZSPLIT), nend = nstart + (N_ / ZSPLIT);
    for (int n0 = nstart; n0 < nend; n0 += CHN) {
        #pragma unroll
        for (int e = tid; e < 512; e += 256) {
            int row = e >> 4, u = e & 15;
            uint4 rq = *(const uint4*)(qbase + (size_t)row * N_ + n0 + u * 8);
            uint4 rk = *(const uint4*)(kbase + (size_t)row * N_ + n0 + u * 8);
            const __half2* hq = (const __half2*)&rq;
            const __half2* hk = (const __half2*)&rk;
            float* dq = &qs[row * PAD + u * 8];
            float* dk = &ks[row * PAD + u * 8];
            #pragma unroll
            for (int w = 0; w < 4; w++) {
                float2 fq = __half22float2(hq[w]);
                float2 fk = __half22float2(hk[w]);
                dq[w * 2] = fq.x; dq[w * 2 + 1] = fq.y;
                dk[w * 2] = fk.x; dk[w * 2 + 1] = fk.y;
            }
        }
        __syncthreads();
        int tb = g * 32;
        #pragma unroll
        for (int s = 0; s < 8; s++) {
            int t = tb + s * 4;
            float4 qv[4], kv[4];
            #pragma unroll
            for (int r = 0; r < 4; r++) qv[r] = *(const float4*)&qs[(ii0 + r) * PAD + t];
            #pragma unroll
            for (int c = 0; c < 4; c++) kv[c] = *(const float4*)&ks[(jj0 + c) * PAD + t];
            #pragma unroll
            for (int r = 0; r < 4; r++)
                #pragma unroll
                for (int c = 0; c < 4; c++)
                    acc[r][c] += qv[r].x * kv[c].x + qv[r].y * kv[c].y
                               + qv[r].z * kv[c].z + qv[r].w * kv[c].w;
        }
        __syncthreads();
    }

    #pragma unroll
    for (int r = 0; r < 4; r++)
        #pragma unroll
        for (int c = 0; c < 4; c++)
            atomicAdd(&simbuf[(ii0 + r) * 32 + jj0 + c], acc[r][c]);
    __syncthreads();

    float* dst = g_simpart + ((size_t)(z * 128 + bh)) * 1024;
    for (int l = tid; l < 1024; l += 256) dst[l] = simbuf[l];
}

// ---------------- Kernel 6: reduce partials + scales + softmax -> attn ----------------
__global__ void softmax_kernel(const float* __restrict__ temp) {
    __shared__ float kinv[32];
    int bh = blockIdx.x;
    int i = threadIdx.x;
    int b = bh >> 3, h = bh & 7;

    float kn = g_norm2[b * 512 + 256 + h * DH + i];
    kinv[i] = 1.0f / fmaxf(sqrtf(kn), L2_EPS);
    float qn = g_norm2[b * 512 + h * DH + i];
    float qsc = expf(temp[h]) / fmaxf(sqrtf(qn), L2_EPS);
    __syncthreads();

    float row[32];
    float mx = -1e30f;
    #pragma unroll 4
    for (int j = 0; j < 32; j++) {
        float v = 0.f;
        #pragma unroll
        for (int z = 0; z < ZSPLIT; z++)
            v += g_simpart[((size_t)(z * 128 + bh)) * 1024 + i * 32 + j];
        v = v * qsc * kinv[j] * XC_SCALE;
        row[j] = v;
        mx = fmaxf(mx, v);
    }
    float sum = 0.f;
    #pragma unroll
    for (int j = 0; j < 32; j++) { row[j] = expf(row[j] - mx); sum += row[j]; }
    float inv = 1.0f / sum;
    #pragma unroll
    for (int j = 0; j < 32; j++)
        g_attn[((size_t)bh * 32 + i) * 32 + j] = row[j] * inv;
}

// ---------------- Kernel 7: attn @ v (fp16 v), fused transpose + bf16 split ----------------
__global__ __launch_bounds__(256) void av_kernel() {
    __shared__ float at[1024];
    __shared__ float tb[32][257];
    int bh = blockIdx.y;
    int b = bh >> 3, h = bh & 7;
    int tid = threadIdx.x;
    int n = blockIdx.x * 256 + tid;

    for (int l = tid; l < 1024; l += 256) at[l] = g_attn[(size_t)bh * 1024 + l];
    __syncthreads();

    const __half* vbase = g_qkvh + ((size_t)b * QKV3 + 512 + h * DH) * N_ + n;

    float acc[32] = {};
    #pragma unroll 4
    for (int j = 0; j < 32; j++) {
        float vj = __half2float(vbase[(size_t)j * N_]);
        #pragma unroll
        for (int i = 0; i < 32; i++) acc[i] += at[i * 32 + j] * vj;
    }
    #pragma unroll
    for (int i = 0; i < 32; i++) tb[i][tid] = acc[i];
    __syncthreads();

    unsigned* outh = (unsigned*)g_avhi;
    unsigned* outl = (unsigned*)g_avlo;
    for (int l = tid; l < 4096; l += 256) {
        int nl = l >> 4, u = l & 15;
        float v0 = tb[u * 2 + 0][nl];
        float v1 = tb[u * 2 + 1][nl];
        __nv_bfloat16 h0 = __float2bfloat16(v0);
        __nv_bfloat16 h1 = __float2bfloat16(v1);
        __nv_bfloat16 l0 = __float2bfloat16(v0 - __bfloat162float(h0));
        __nv_bfloat16 l1 = __float2bfloat16(v1 - __bfloat162float(h1));
        int gn = blockIdx.x * 256 + nl;
        size_t idx = ((size_t)(b * 4096 + gn)) * 128 + h * 16 + u;
        outh[idx] = (unsigned)__bfloat16_as_ushort(h0) | ((unsigned)__bfloat16_as_ushort(h1) << 16);
        outl[idx] = (unsigned)__bfloat16_as_ushort(l0) | ((unsigned)__bfloat16_as_ushort(l1) << 16);
    }
}

// ---------------- launch ----------------
extern "C" void kernel_launch(void* const* d_in, const int* in_sizes, int n_in,
                              void* d_out, int out_size) {
    const float* x     = (const float*)d_in[0];
    const float* gamma = (const float*)d_in[1];
    const float* beta  = (const float*)d_in[2];
    const float* Wqkv  = (const float*)d_in[3];
    const float* temp  = (const float*)d_in[4];
    const float* Wout  = (const float*)d_in[5];
    const float* bout  = (const float*)d_in[6];
    float* out = (float*)d_out;
    (void)in_sizes; (void)n_in; (void)out_size;

    cudaFuncSetAttribute(mgemm_kernel, cudaFuncAttributeMaxDynamicSharedMemorySize, 2 * STG);

    zero_kernel<<<32, 256>>>();
    lnconv_kernel<<<dim3(N_ / 32, B_), 256>>>(x, gamma, beta);
    wsplit_kernel<<<256, dim3(32, 8)>>>(Wqkv, Wout);
    // QKV projection (HMMA) -> fp16 q,k,v + fused norms
    mgemm_kernel<<<dim3(N_ / 128, QKV3 / 128, B_), 256, 2 * STG>>>(0, nullptr, nullptr, QKV3);
    // sim partials + softmax
    sim_part_kernel<<<dim3(B_ * HEADS, ZSPLIT), 256>>>();
    softmax_kernel<<<B_ * HEADS, 32>>>(temp);
    // attn @ v
    av_kernel<<<dim3(N_ / 256, B_ * HEADS), 256>>>();
    // output projection + bias -> d_out
    mgemm_kernel<<<dim3(N_ / 128, C_ / 128, B_), 256, 2 * STG>>>(1, out, bout, C_);
}

// round 9
// speedup vs baseline: 1.0077x; 1.0077x over previous
#include <cuda_runtime.h>
#include <cuda_bf16.h>
#include <math.h>
#include <stdint.h>

#define B_    16
#define C_    256
#define N_    4096
#define HEADS 8
#define DH    32
#define QKV3  768
#define LN_EPS 1e-5f
#define L2_EPS 1e-12f
#define XC_SCALE 8.0f
#define ZSPLIT 8

// ---------------- scratch ----------------
__device__ __nv_bfloat16 g_thi[(size_t)B_ * N_ * C_];
__device__ __nv_bfloat16 g_tlo[(size_t)B_ * N_ * C_];
__device__ float g_qkv[(size_t)B_ * QKV3 * N_];
__device__ float g_qscale[B_ * C_];
__device__ float g_kscale[B_ * C_];
__device__ float g_simpart[ZSPLIT * B_ * HEADS * DH * DH];
__device__ float g_attn[B_ * HEADS * DH * DH];
__device__ __nv_bfloat16 g_avhi[(size_t)B_ * N_ * C_];
__device__ __nv_bfloat16 g_avlo[(size_t)B_ * N_ * C_];
__device__ __nv_bfloat16 g_wqh[QKV3 * C_];
__device__ __nv_bfloat16 g_wql[QKV3 * C_];
__device__ __nv_bfloat16 g_woh[C_ * C_];
__device__ __nv_bfloat16 g_wol[C_ * C_];

__device__ __forceinline__ uint32_t smem_u32(const void* p) {
    uint32_t a;
    asm("{ .reg .u64 t; cvta.to.shared.u64 t, %1; cvt.u32.u64 %0, t; }" : "=r"(a) : "l"(p));
    return a;
}
__device__ __forceinline__ void mma_bf16(float* c, const uint32_t* a, const uint32_t* b) {
    asm volatile("mma.sync.aligned.m16n8k16.row.col.f32.bf16.bf16.f32 "
                 "{%0,%1,%2,%3}, {%4,%5,%6,%7}, {%8,%9}, {%0,%1,%2,%3};"
                 : "+f"(c[0]), "+f"(c[1]), "+f"(c[2]), "+f"(c[3])
                 : "r"(a[0]), "r"(a[1]), "r"(a[2]), "r"(a[3]), "r"(b[0]), "r"(b[1]));
}
__device__ __forceinline__ void ldsm4(uint32_t* r, uint32_t addr) {
    asm volatile("ldmatrix.sync.aligned.m8n8.x4.shared.b16 {%0,%1,%2,%3}, [%4];"
                 : "=r"(r[0]), "=r"(r[1]), "=r"(r[2]), "=r"(r[3]) : "r"(addr));
}
__device__ __forceinline__ void cp16(uint32_t sa, const void* ga) {
    asm volatile("cp.async.cg.shared.global [%0], [%1], 16;" :: "r"(sa), "l"(ga) : "memory");
}
#define CP_COMMIT() asm volatile("cp.async.commit_group;" ::: "memory")
#define CP_WAIT1()  asm volatile("cp.async.wait_group 1;" ::: "memory")
#define CP_WAIT0()  asm volatile("cp.async.wait_group 0;" ::: "memory")

// ---------------- Kernel 1: fused LayerNorm + transpose + bf16 split ----------------
__global__ __launch_bounds__(256) void lnconv_kernel(const float* __restrict__ x,
                                                     const float* __restrict__ gamma,
                                                     const float* __restrict__ beta) {
    __shared__ float s[256][33];
    __shared__ float p1[8][32], p2[8][32];
    __shared__ float mu_s[32], rs_s[32];
    int tid = threadIdx.x;
    int b = blockIdx.y, n0 = blockIdx.x * 32;
    int nl = tid & 31, g = tid >> 5;

    float a1 = 0.f, a2 = 0.f;
    for (int c = g; c < 256; c += 8) {
        float v = x[((size_t)b * 256 + c) * 4096 + n0 + nl];
        s[c][nl] = v;
        a1 += v; a2 += v * v;
    }
    p1[g][nl] = a1; p2[g][nl] = a2;
    __syncthreads();
    if (tid < 32) {
        float s1 = 0.f, s2 = 0.f;
        #pragma unroll
        for (int gg = 0; gg < 8; gg++) { s1 += p1[gg][tid]; s2 += p2[gg][tid]; }
        float mu = s1 * (1.0f / 256.0f);
        float var = s2 * (1.0f / 256.0f) - mu * mu;
        mu_s[tid] = mu;
        rs_s[tid] = rsqrtf(var + LN_EPS);
    }
    __syncthreads();

    float gm = gamma[tid], bt = beta[tid];
    #pragma unroll 4
    for (int n = 0; n < 32; n++) {
        float v = (s[tid][n] - mu_s[n]) * rs_s[n] * gm + bt;
        __nv_bfloat16 h = __float2bfloat16(v);
        __nv_bfloat16 l = __float2bfloat16(v - __bfloat162float(h));
        size_t o = ((size_t)b * 4096 + n0 + n) * 256 + tid;
        g_thi[o] = h;
        g_tlo[o] = l;
    }
}

// ---------------- Kernel 2: weight transpose + split (single launch) ----------------
__global__ void wsplit_kernel(const float* __restrict__ Wq, const float* __restrict__ Wo) {
    __shared__ float tb[32][33];
    int bid = blockIdx.x;
    const float* W;
    __nv_bfloat16 *hi, *lo;
    int M, m0, k0;
    if (bid < 192) {                    // Wqkv: 24 x 8 tiles
        W = Wq; hi = g_wqh; lo = g_wql; M = QKV3;
        m0 = (bid % 24) * 32; k0 = (bid / 24) * 32;
    } else {                            // Wout: 8 x 8 tiles
        bid -= 192;
        W = Wo; hi = g_woh; lo = g_wol; M = C_;
        m0 = (bid % 8) * 32; k0 = (bid / 8) * 32;
    }
    int tx = threadIdx.x, ty = threadIdx.y;
    for (int r = ty; r < 32; r += 8)
        tb[r][tx] = W[(size_t)(k0 + r) * M + m0 + tx];
    __syncthreads();
    for (int r = ty; r < 32; r += 8) {
        float v = tb[tx][r];
        __nv_bfloat16 h = __float2bfloat16(v);
        __nv_bfloat16 l = __float2bfloat16(v - __bfloat162float(h));
        size_t o = (size_t)(m0 + r) * 256 + k0 + tx;
        hi[o] = h; lo[o] = l;
    }
}

// ---------------- Kernel 3: 3-stage pipelined ldmatrix split-bf16 HMMA GEMM ----------------
// Block 128(m) x 128(j). K=256, 8 chunks of 32. 3-stage cp.async ring, 1 barrier/chunk.
#define STG 32768
#define GSMEM (3 * STG)

__global__ __launch_bounds__(256) void mgemm_kernel(int mode, float* __restrict__ out_ext,
                                                    const float* __restrict__ bias, int Mtotal) {
    extern __shared__ char sm[];
    uint32_t smb = smem_u32(sm);

    int tid = threadIdx.x, wid = tid >> 5, lane = tid & 31;
    int qrow = lane >> 2, qcol = lane & 3;
    int warp_m = wid >> 2;
    int warp_n = wid & 3;
    int n0 = blockIdx.x * 128, j0 = blockIdx.y * 128, b = blockIdx.z;

    const uint4* Agh = (const uint4*)(mode == 0 ? g_thi : g_avhi);
    const uint4* Agl = (const uint4*)(mode == 0 ? g_tlo : g_avlo);
    const uint4* Bgh = (const uint4*)(mode == 0 ? g_wqh : g_woh);
    const uint4* Bgl = (const uint4*)(mode == 0 ? g_wql : g_wol);
    float* C = (mode == 0) ? g_qkv : out_ext;

    int lr0 = tid >> 2;
    int lc = tid & 3;
    uint32_t so0 = (uint32_t)(lr0 * 64 + ((lc ^ ((lr0 >> 1) & 3)) * 16));
    int lr1 = lr0 + 64;
    uint32_t so1 = (uint32_t)(lr1 * 64 + ((lc ^ ((lr1 >> 1) & 3)) * 16));

    size_t gaBase0 = ((size_t)(b * 4096 + n0 + lr0)) * 32 + lc;
    size_t gaBase1 = ((size_t)(b * 4096 + n0 + lr1)) * 32 + lc;
    size_t gbBase0 = ((size_t)(j0 + lr0)) * 32 + lc;
    size_t gbBase1 = ((size_t)(j0 + lr1)) * 32 + lc;

    float acc[4][4][4] = {};

    // prologue: chunks 0,1 into stages 0,1
    #pragma unroll
    for (int pc = 0; pc < 2; pc++) {
        uint32_t st = smb + pc * STG;
        int k8 = pc * 4;
        cp16(st + so0,          Agh + gaBase0 + k8);
        cp16(st + so1,          Agh + gaBase1 + k8);
        cp16(st + 8192 + so0,   Agl + gaBase0 + k8);
        cp16(st + 8192 + so1,   Agl + gaBase1 + k8);
        cp16(st + 16384 + so0,  Bgh + gbBase0 + k8);
        cp16(st + 16384 + so1,  Bgh + gbBase1 + k8);
        cp16(st + 24576 + so0,  Bgl + gbBase0 + k8);
        cp16(st + 24576 + so1,  Bgl + gbBase1 + k8);
        CP_COMMIT();
    }

    int aRow = (lane & 15);
    int aCol = lane >> 4;
    int bRow = ((lane >> 4) << 3) + (lane & 7);
    int bCol = (lane >> 3) & 1;

    int cur = 0, nxt2 = 2;   // stage indices: compute stage, stage to fill (chunk+2)
    for (int chunk = 0; chunk < 8; chunk++) {
        if (chunk < 7) CP_WAIT1(); else CP_WAIT0();
        __syncthreads();

        if (chunk < 6) {
            int k8 = (chunk + 2) * 4;
            uint32_t st = smb + nxt2 * STG;
            cp16(st + so0,          Agh + gaBase0 + k8);
            cp16(st + so1,          Agh + gaBase1 + k8);
            cp16(st + 8192 + so0,   Agl + gaBase0 + k8);
            cp16(st + 8192 + so1,   Agl + gaBase1 + k8);
            cp16(st + 16384 + so0,  Bgh + gbBase0 + k8);
            cp16(st + 16384 + so1,  Bgh + gbBase1 + k8);
            cp16(st + 24576 + so0,  Bgl + gbBase0 + k8);
            cp16(st + 24576 + so1,  Bgl + gbBase1 + k8);
            CP_COMMIT();
        }

        uint32_t st = smb + cur * STG;
        #pragma unroll
        for (int kk = 0; kk < 2; kk++) {
            uint32_t bh[2][4], bl[2][4];
            #pragma unroll
            for (int np = 0; np < 2; np++) {
                int row = warp_n * 32 + np * 16 + bRow;
                uint32_t cc = (uint32_t)(((kk * 2) | bCol) ^ ((row >> 1) & 3));
                uint32_t ad = st + 16384 + (uint32_t)(row * 64) + cc * 16;
                ldsm4(bh[np], ad);
                ldsm4(bl[np], ad + 8192);
            }
            #pragma unroll
            for (int mf = 0; mf < 4; mf++) {
                int row = warp_m * 64 + mf * 16 + aRow;
                uint32_t cc = (uint32_t)(((kk * 2) | aCol) ^ ((row >> 1) & 3));
                uint32_t ad = st + (uint32_t)(row * 64) + cc * 16;
                uint32_t ah[4], al[4];
                ldsm4(ah, ad);
                ldsm4(al, ad + 8192);
                #pragma unroll
                for (int nf = 0; nf < 4; nf++) {
                    const uint32_t* bhf = &bh[nf >> 1][(nf & 1) * 2];
                    const uint32_t* blf = &bl[nf >> 1][(nf & 1) * 2];
                    mma_bf16(acc[mf][nf], ah, bhf);
                    mma_bf16(acc[mf][nf], ah, blf);
                    mma_bf16(acc[mf][nf], al, bhf);
                }
            }
        }
        cur = (cur == 2) ? 0 : cur + 1;
        nxt2 = (nxt2 == 2) ? 0 : nxt2 + 1;
    }

    // direct transposed stores (R5 layout)
    #pragma unroll
    for (int mf = 0; mf < 4; mf++) {
        int m = n0 + warp_m * 64 + mf * 16 + qrow;
        #pragma unroll
        for (int nf = 0; nf < 4; nf++) {
            int j = j0 + warp_n * 32 + nf * 8 + qcol * 2;
            float b0 = bias ? bias[j] : 0.f;
            float b1 = bias ? bias[j + 1] : 0.f;
            size_t r0 = ((size_t)b * Mtotal + j) * 4096 + m;
            size_t r1 = r0 + 4096;
            C[r0]     = acc[mf][nf][0] + b0;
            C[r1]     = acc[mf][nf][1] + b1;
            C[r0 + 8] = acc[mf][nf][2] + b0;
            C[r1 + 8] = acc[mf][nf][3] + b1;
        }
    }
}

// ---------------- Kernel 4: q/k row L2 norms -> scales ----------------
__global__ void norm_kernel(const float* __restrict__ temp) {
    int j = blockIdx.x, b = blockIdx.y, which = blockIdx.z;
    int tid = threadIdx.x;
    const float* row = g_qkv + ((size_t)b * QKV3 + which * 256 + j) * N_;
    float s = 0.f;
    for (int n = tid * 4; n < N_; n += 512) {
        float4 v = *(const float4*)&row[n];
        s += v.x * v.x + v.y * v.y + v.z * v.z + v.w * v.w;
    }
    #pragma unroll
    for (int o = 16; o > 0; o >>= 1) s += __shfl_down_sync(0xffffffffu, s, o);
    __shared__ float ws[4];
    if ((tid & 31) == 0) ws[tid >> 5] = s;
    __syncthreads();
    if (tid == 0) {
        float tot = ws[0] + ws[1] + ws[2] + ws[3];
        float d = fmaxf(sqrtf(tot), L2_EPS);
        float sc = (which == 0) ? (expf(temp[j >> 5]) / d) : (1.0f / d);
        if (which == 0) g_qscale[b * C_ + j] = sc;
        else            g_kscale[b * C_ + j] = sc;
    }
}

// ---------------- Kernel 5: sim partials (split-K x ZSPLIT) ----------------
#define CHN 128
#define PAD 132
__global__ void sim_part_kernel() {
    __shared__ float qs[32 * PAD];
    __shared__ float ks[32 * PAD];
    __shared__ float simbuf[32 * 32];

    int bh = blockIdx.x, z = blockIdx.y;
    int b = bh >> 3, h = bh & 7;
    int tid = threadIdx.x;
    const float* qbase = g_qkv + ((size_t)b * QKV3 + h * DH) * N_;
    const float* kbase = g_qkv + ((size_t)b * QKV3 + 256 + h * DH) * N_;

    for (int l = tid; l < 1024; l += 256) simbuf[l] = 0.f;

    int g = tid >> 6;
    int p = tid & 63;
    int ii0 = (p >> 3) * 4;
    int jj0 = (p & 7) * 4;
    float acc[4][4] = {};

    int nstart = z * (N_ / ZSPLIT), nend = nstart + (N_ / ZSPLIT);
    for (int n0 = nstart; n0 < nend; n0 += CHN) {
        for (int e = tid * 4; e < 32 * CHN; e += 1024) {
            int row = e >> 7, t = e & (CHN - 1);
            *(float4*)&qs[row * PAD + t] = *(const float4*)&qbase[(size_t)row * N_ + n0 + t];
            *(float4*)&ks[row * PAD + t] = *(const float4*)&kbase[(size_t)row * N_ + n0 + t];
        }
        __syncthreads();
        int tb = g * 32;
        #pragma unroll
        for (int s = 0; s < 8; s++) {
            int t = tb + s * 4;
            float4 qv[4], kv[4];
            #pragma unroll
            for (int r = 0; r < 4; r++) qv[r] = *(const float4*)&qs[(ii0 + r) * PAD + t];
            #pragma unroll
            for (int c = 0; c < 4; c++) kv[c] = *(const float4*)&ks[(jj0 + c) * PAD + t];
            #pragma unroll
            for (int r = 0; r < 4; r++)
                #pragma unroll
                for (int c = 0; c < 4; c++)
                    acc[r][c] += qv[r].x * kv[c].x + qv[r].y * kv[c].y
                               + qv[r].z * kv[c].z + qv[r].w * kv[c].w;
        }
        __syncthreads();
    }

    #pragma unroll
    for (int r = 0; r < 4; r++)
        #pragma unroll
        for (int c = 0; c < 4; c++)
            atomicAdd(&simbuf[(ii0 + r) * 32 + jj0 + c], acc[r][c]);
    __syncthreads();

    float* dst = g_simpart + ((size_t)(z * 128 + bh)) * 1024;
    for (int l = tid; l < 1024; l += 256) dst[l] = simbuf[l];
}

// ---------------- Kernel 6: reduce partials + softmax -> attn ----------------
__global__ void softmax_kernel() {
    int bh = blockIdx.x;
    int i = threadIdx.x;
    int b = bh >> 3, h = bh & 7;
    float qsc = g_qscale[b * C_ + h * DH + i];
    float row[32];
    float mx = -1e30f;
    #pragma unroll 4
    for (int j = 0; j < 32; j++) {
        float v = 0.f;
        #pragma unroll
        for (int z = 0; z < ZSPLIT; z++)
            v += g_simpart[((size_t)(z * 128 + bh)) * 1024 + i * 32 + j];
        v = v * qsc * g_kscale[b * C_ + h * DH + j] * XC_SCALE;
        row[j] = v;
        mx = fmaxf(mx, v);
    }
    float sum = 0.f;
    #pragma unroll
    for (int j = 0; j < 32; j++) { row[j] = expf(row[j] - mx); sum += row[j]; }
    float inv = 1.0f / sum;
    #pragma unroll
    for (int j = 0; j < 32; j++)
        g_attn[((size_t)bh * 32 + i) * 32 + j] = row[j] * inv;
}

// ---------------- Kernel 7: attn @ v, fused transpose + bf16 split ----------------
__global__ __launch_bounds__(256) void av_kernel() {
    __shared__ float at[1024];
    __shared__ float tb[32][257];
    int bh = blockIdx.y;
    int b = bh >> 3, h = bh & 7;
    int tid = threadIdx.x;
    int n = blockIdx.x * 256 + tid;

    for (int l = tid; l < 1024; l += 256) at[l] = g_attn[(size_t)bh * 1024 + l];
    __syncthreads();

    const float* vbase = g_qkv + ((size_t)b * QKV3 + 512 + h * DH) * N_ + n;

    float acc[32] = {};
    #pragma unroll 4
    for (int j = 0; j < 32; j++) {
        float vj = vbase[(size_t)j * N_];
        #pragma unroll
        for (int i = 0; i < 32; i++) acc[i] += at[i * 32 + j] * vj;
    }
    #pragma unroll
    for (int i = 0; i < 32; i++) tb[i][tid] = acc[i];
    __syncthreads();

    unsigned* outh = (unsigned*)g_avhi;
    unsigned* outl = (unsigned*)g_avlo;
    for (int l = tid; l < 4096; l += 256) {
        int nl = l >> 4, u = l & 15;
        float v0 = tb[u * 2 + 0][nl];
        float v1 = tb[u * 2 + 1][nl];
        __nv_bfloat16 h0 = __float2bfloat16(v0);
        __nv_bfloat16 h1 = __float2bfloat16(v1);
        __nv_bfloat16 l0 = __float2bfloat16(v0 - __bfloat162float(h0));
        __nv_bfloat16 l1 = __float2bfloat16(v1 - __bfloat162float(h1));
        int gn = blockIdx.x * 256 + nl;
        size_t idx = ((size_t)(b * 4096 + gn)) * 128 + h * 16 + u;
        outh[idx] = (unsigned)__bfloat16_as_ushort(h0) | ((unsigned)__bfloat16_as_ushort(h1) << 16);
        outl[idx] = (unsigned)__bfloat16_as_ushort(l0) | ((unsigned)__bfloat16_as_ushort(l1) << 16);
    }
}

// ---------------- launch ----------------
extern "C" void kernel_launch(void* const* d_in, const int* in_sizes, int n_in,
                              void* d_out, int out_size) {
    const float* x     = (const float*)d_in[0];
    const float* gamma = (const float*)d_in[1];
    const float* beta  = (const float*)d_in[2];
    const float* Wqkv  = (const float*)d_in[3];
    const float* temp  = (const float*)d_in[4];
    const float* Wout  = (const float*)d_in[5];
    const float* bout  = (const float*)d_in[6];
    float* out = (float*)d_out;
    (void)in_sizes; (void)n_in; (void)out_size;

    cudaFuncSetAttribute(mgemm_kernel, cudaFuncAttributeMaxDynamicSharedMemorySize, GSMEM);

    lnconv_kernel<<<dim3(N_ / 32, B_), 256>>>(x, gamma, beta);
    wsplit_kernel<<<256, dim3(32, 8)>>>(Wqkv, Wout);
    // QKV projection (3-stage pipelined HMMA)
    mgemm_kernel<<<dim3(N_ / 128, QKV3 / 128, B_), 256, GSMEM>>>(0, nullptr, nullptr, QKV3);
    // q/k norms -> scales
    norm_kernel<<<dim3(C_, B_, 2), 128>>>(temp);
    // sim partials + softmax
    sim_part_kernel<<<dim3(B_ * HEADS, ZSPLIT), 256>>>();
    softmax_kernel<<<B_ * HEADS, 32>>>();
    // attn @ v
    av_kernel<<<dim3(N_ / 256, B_ * HEADS), 256>>>();
    // output projection + bias -> d_out
    mgemm_kernel<<<dim3(N_ / 128, C_ / 128, B_), 256, GSMEM>>>(1, out, bout, C_);
}

// round 10
// speedup vs baseline: 1.0726x; 1.0644x over previous
#include <cuda_runtime.h>
#include <cuda_bf16.h>
#include <math.h>
#include <stdint.h>

#define B_    16
#define C_    256
#define N_    4096
#define HEADS 8
#define DH    32
#define QKV3  768
#define LN_EPS 1e-5f
#define L2_EPS 1e-12f
#define XC_SCALE 8.0f
#define ZSPLIT 8

// ---------------- scratch ----------------
__device__ __nv_bfloat16 g_thi[(size_t)B_ * N_ * C_];
__device__ __nv_bfloat16 g_tlo[(size_t)B_ * N_ * C_];
__device__ float g_qkv[(size_t)B_ * QKV3 * N_];
__device__ float g_norm2[B_ * 512];                       // q(0..255), k(256..511) sumsq
__device__ float g_simpart[ZSPLIT * B_ * HEADS * DH * DH];
__device__ float g_attn[B_ * HEADS * DH * DH];
__device__ __nv_bfloat16 g_avhi[(size_t)B_ * N_ * C_];
__device__ __nv_bfloat16 g_avlo[(size_t)B_ * N_ * C_];
__device__ __nv_bfloat16 g_wqh[QKV3 * C_];
__device__ __nv_bfloat16 g_wql[QKV3 * C_];
__device__ __nv_bfloat16 g_woh[C_ * C_];
__device__ __nv_bfloat16 g_wol[C_ * C_];

__device__ __forceinline__ uint32_t smem_u32(const void* p) {
    uint32_t a;
    asm("{ .reg .u64 t; cvta.to.shared.u64 t, %1; cvt.u32.u64 %0, t; }" : "=r"(a) : "l"(p));
    return a;
}
__device__ __forceinline__ void mma_bf16(float* c, const uint32_t* a, const uint32_t* b) {
    asm volatile("mma.sync.aligned.m16n8k16.row.col.f32.bf16.bf16.f32 "
                 "{%0,%1,%2,%3}, {%4,%5,%6,%7}, {%8,%9}, {%0,%1,%2,%3};"
                 : "+f"(c[0]), "+f"(c[1]), "+f"(c[2]), "+f"(c[3])
                 : "r"(a[0]), "r"(a[1]), "r"(a[2]), "r"(a[3]), "r"(b[0]), "r"(b[1]));
}
__device__ __forceinline__ void ldsm4(uint32_t* r, uint32_t addr) {
    asm volatile("ldmatrix.sync.aligned.m8n8.x4.shared.b16 {%0,%1,%2,%3}, [%4];"
                 : "=r"(r[0]), "=r"(r[1]), "=r"(r[2]), "=r"(r[3]) : "r"(addr));
}
__device__ __forceinline__ void cp16(uint32_t sa, const void* ga) {
    asm volatile("cp.async.cg.shared.global [%0], [%1], 16;" :: "r"(sa), "l"(ga) : "memory");
}
#define CP_COMMIT() asm volatile("cp.async.commit_group;" ::: "memory")
#define CP_WAIT1()  asm volatile("cp.async.wait_group 1;" ::: "memory")
#define CP_WAIT0()  asm volatile("cp.async.wait_group 0;" ::: "memory")

// ---------------- Kernel 0: zero norm accumulators ----------------
__global__ void zero_kernel() {
    int i = blockIdx.x * 256 + threadIdx.x;
    if (i < B_ * 512) g_norm2[i] = 0.f;
}

// ---------------- Kernel 1: fused LayerNorm + transpose + bf16 split ----------------
__global__ __launch_bounds__(256) void lnconv_kernel(const float* __restrict__ x,
                                                     const float* __restrict__ gamma,
                                                     const float* __restrict__ beta) {
    __shared__ float s[256][33];
    __shared__ float p1[8][32], p2[8][32];
    __shared__ float mu_s[32], rs_s[32];
    int tid = threadIdx.x;
    int b = blockIdx.y, n0 = blockIdx.x * 32;
    int nl = tid & 31, g = tid >> 5;

    float a1 = 0.f, a2 = 0.f;
    for (int c = g; c < 256; c += 8) {
        float v = x[((size_t)b * 256 + c) * 4096 + n0 + nl];
        s[c][nl] = v;
        a1 += v; a2 += v * v;
    }
    p1[g][nl] = a1; p2[g][nl] = a2;
    __syncthreads();
    if (tid < 32) {
        float s1 = 0.f, s2 = 0.f;
        #pragma unroll
        for (int gg = 0; gg < 8; gg++) { s1 += p1[gg][tid]; s2 += p2[gg][tid]; }
        float mu = s1 * (1.0f / 256.0f);
        float var = s2 * (1.0f / 256.0f) - mu * mu;
        mu_s[tid] = mu;
        rs_s[tid] = rsqrtf(var + LN_EPS);
    }
    __syncthreads();

    float gm = gamma[tid], bt = beta[tid];
    #pragma unroll 4
    for (int n = 0; n < 32; n++) {
        float v = (s[tid][n] - mu_s[n]) * rs_s[n] * gm + bt;
        __nv_bfloat16 h = __float2bfloat16(v);
        __nv_bfloat16 l = __float2bfloat16(v - __bfloat162float(h));
        size_t o = ((size_t)b * 4096 + n0 + n) * 256 + tid;
        g_thi[o] = h;
        g_tlo[o] = l;
    }
}

// ---------------- Kernel 2: weight transpose + split (single launch) ----------------
__global__ void wsplit_kernel(const float* __restrict__ Wq, const float* __restrict__ Wo) {
    __shared__ float tb[32][33];
    int bid = blockIdx.x;
    const float* W;
    __nv_bfloat16 *hi, *lo;
    int M, m0, k0;
    if (bid < 192) {                    // Wqkv: 24 x 8 tiles
        W = Wq; hi = g_wqh; lo = g_wql; M = QKV3;
        m0 = (bid % 24) * 32; k0 = (bid / 24) * 32;
    } else {                            // Wout: 8 x 8 tiles
        bid -= 192;
        W = Wo; hi = g_woh; lo = g_wol; M = C_;
        m0 = (bid % 8) * 32; k0 = (bid / 8) * 32;
    }
    int tx = threadIdx.x, ty = threadIdx.y;
    for (int r = ty; r < 32; r += 8)
        tb[r][tx] = W[(size_t)(k0 + r) * M + m0 + tx];
    __syncthreads();
    for (int r = ty; r < 32; r += 8) {
        float v = tb[tx][r];
        __nv_bfloat16 h = __float2bfloat16(v);
        __nv_bfloat16 l = __float2bfloat16(v - __bfloat162float(h));
        size_t o = (size_t)(m0 + r) * 256 + k0 + tx;
        hi[o] = h; lo[o] = l;
    }
}

// ---------------- Kernel 3: 2-stage pipelined ldmatrix split-bf16 HMMA GEMM (R5) ----------------
#define STG 32768

__global__ __launch_bounds__(256) void mgemm_kernel(int mode, float* __restrict__ out_ext,
                                                    const float* __restrict__ bias, int Mtotal) {
    extern __shared__ char sm[];
    uint32_t smb = smem_u32(sm);

    int tid = threadIdx.x, wid = tid >> 5, lane = tid & 31;
    int qrow = lane >> 2, qcol = lane & 3;
    int warp_m = wid >> 2;
    int warp_n = wid & 3;
    int n0 = blockIdx.x * 128, j0 = blockIdx.y * 128, b = blockIdx.z;

    const uint4* Agh = (const uint4*)(mode == 0 ? g_thi : g_avhi);
    const uint4* Agl = (const uint4*)(mode == 0 ? g_tlo : g_avlo);
    const uint4* Bgh = (const uint4*)(mode == 0 ? g_wqh : g_woh);
    const uint4* Bgl = (const uint4*)(mode == 0 ? g_wql : g_wol);
    float* C = (mode == 0) ? g_qkv : out_ext;

    int lr0 = tid >> 2;
    int lc = tid & 3;
    uint32_t so0 = (uint32_t)(lr0 * 64 + ((lc ^ ((lr0 >> 1) & 3)) * 16));
    int lr1 = lr0 + 64;
    uint32_t so1 = (uint32_t)(lr1 * 64 + ((lc ^ ((lr1 >> 1) & 3)) * 16));

    float acc[4][4][4] = {};

    {
        size_t ga0 = ((size_t)(b * 4096 + n0 + lr0)) * 32 + lc;
        size_t ga1 = ((size_t)(b * 4096 + n0 + lr1)) * 32 + lc;
        size_t gb0 = ((size_t)(j0 + lr0)) * 32 + lc;
        size_t gb1 = ((size_t)(j0 + lr1)) * 32 + lc;
        cp16(smb + so0,         Agh + ga0);
        cp16(smb + so1,         Agh + ga1);
        cp16(smb + 8192 + so0,  Agl + ga0);
        cp16(smb + 8192 + so1,  Agl + ga1);
        cp16(smb + 16384 + so0, Bgh + gb0);
        cp16(smb + 16384 + so1, Bgh + gb1);
        cp16(smb + 24576 + so0, Bgl + gb0);
        cp16(smb + 24576 + so1, Bgl + gb1);
        CP_COMMIT();
    }

    int aRow = (lane & 15);
    int aCol = lane >> 4;
    int bRow = ((lane >> 4) << 3) + (lane & 7);
    int bCol = (lane >> 3) & 1;

    for (int chunk = 0; chunk < 8; chunk++) {
        if (chunk < 7) {
            int k8 = (chunk + 1) * 4;
            uint32_t st = smb + ((chunk + 1) & 1) * STG;
            size_t ga0 = ((size_t)(b * 4096 + n0 + lr0)) * 32 + k8 + lc;
            size_t ga1 = ((size_t)(b * 4096 + n0 + lr1)) * 32 + k8 + lc;
            size_t gb0 = ((size_t)(j0 + lr0)) * 32 + k8 + lc;
            size_t gb1 = ((size_t)(j0 + lr1)) * 32 + k8 + lc;
            cp16(st + so0,          Agh + ga0);
            cp16(st + so1,          Agh + ga1);
            cp16(st + 8192 + so0,   Agl + ga0);
            cp16(st + 8192 + so1,   Agl + ga1);
            cp16(st + 16384 + so0,  Bgh + gb0);
            cp16(st + 16384 + so1,  Bgh + gb1);
            cp16(st + 24576 + so0,  Bgl + gb0);
            cp16(st + 24576 + so1,  Bgl + gb1);
            CP_COMMIT();
            CP_WAIT1();
        } else {
            CP_WAIT0();
        }
        __syncthreads();

        uint32_t st = smb + (chunk & 1) * STG;
        #pragma unroll
        for (int kk = 0; kk < 2; kk++) {
            uint32_t bh[2][4], bl[2][4];
            #pragma unroll
            for (int np = 0; np < 2; np++) {
                int row = warp_n * 32 + np * 16 + bRow;
                uint32_t cc = (uint32_t)(((kk * 2) | bCol) ^ ((row >> 1) & 3));
                uint32_t ad = st + 16384 + (uint32_t)(row * 64) + cc * 16;
                ldsm4(bh[np], ad);
                ldsm4(bl[np], ad + 8192);
            }
            #pragma unroll
            for (int mf = 0; mf < 4; mf++) {
                int row = warp_m * 64 + mf * 16 + aRow;
                uint32_t cc = (uint32_t)(((kk * 2) | aCol) ^ ((row >> 1) & 3));
                uint32_t ad = st + (uint32_t)(row * 64) + cc * 16;
                uint32_t ah[4], al[4];
                ldsm4(ah, ad);
                ldsm4(al, ad + 8192);
                #pragma unroll
                for (int nf = 0; nf < 4; nf++) {
                    const uint32_t* bhf = &bh[nf >> 1][(nf & 1) * 2];
                    const uint32_t* blf = &bl[nf >> 1][(nf & 1) * 2];
                    mma_bf16(acc[mf][nf], ah, bhf);
                    mma_bf16(acc[mf][nf], ah, blf);
                    mma_bf16(acc[mf][nf], al, bhf);
                }
            }
        }
        __syncthreads();
    }

    #pragma unroll
    for (int mf = 0; mf < 4; mf++) {
        int m = n0 + warp_m * 64 + mf * 16 + qrow;
        #pragma unroll
        for (int nf = 0; nf < 4; nf++) {
            int j = j0 + warp_n * 32 + nf * 8 + qcol * 2;
            float b0 = bias ? bias[j] : 0.f;
            float b1 = bias ? bias[j + 1] : 0.f;
            size_t r0 = ((size_t)b * Mtotal + j) * 4096 + m;
            size_t r1 = r0 + 4096;
            C[r0]     = acc[mf][nf][0] + b0;
            C[r1]     = acc[mf][nf][1] + b1;
            C[r0 + 8] = acc[mf][nf][2] + b0;
            C[r1 + 8] = acc[mf][nf][3] + b1;
        }
    }
}

// ---------------- Kernel 5: sim partials + fused q/k norm partials ----------------
#define CHN 128
#define PAD 132
__global__ void sim_part_kernel() {
    __shared__ float qs[32 * PAD];
    __shared__ float ks[32 * PAD];
    __shared__ float simbuf[32 * 32];

    int bh = blockIdx.x, z = blockIdx.y;
    int b = bh >> 3, h = bh & 7;
    int tid = threadIdx.x;
    const float* qbase = g_qkv + ((size_t)b * QKV3 + h * DH) * N_;
    const float* kbase = g_qkv + ((size_t)b * QKV3 + 256 + h * DH) * N_;

    for (int l = tid; l < 1024; l += 256) simbuf[l] = 0.f;

    int g = tid >> 6;
    int p = tid & 63;
    int ii0 = (p >> 3) * 4;
    int jj0 = (p & 7) * 4;
    float acc[4][4] = {};
    float qacc = 0.f, kacc = 0.f;     // norm partials: row = tid>>3, seg = tid&7

    int nrow = tid >> 3;
    int nseg = (tid & 7) * 16;

    int nstart = z * (N_ / ZSPLIT), nend = nstart + (N_ / ZSPLIT);
    for (int n0 = nstart; n0 < nend; n0 += CHN) {
        for (int e = tid * 4; e < 32 * CHN; e += 1024) {
            int row = e >> 7, t = e & (CHN - 1);
            *(float4*)&qs[row * PAD + t] = *(const float4*)&qbase[(size_t)row * N_ + n0 + t];
            *(float4*)&ks[row * PAD + t] = *(const float4*)&kbase[(size_t)row * N_ + n0 + t];
        }
        __syncthreads();

        // fused norm pass: 8 threads per row, 16 elements each
        {
            const float* qp = &qs[nrow * PAD + nseg];
            const float* kp = &ks[nrow * PAD + nseg];
            #pragma unroll
            for (int u = 0; u < 16; u += 4) {
                float4 a = *(const float4*)&qp[u];
                float4 c = *(const float4*)&kp[u];
                qacc += a.x * a.x + a.y * a.y + a.z * a.z + a.w * a.w;
                kacc += c.x * c.x + c.y * c.y + c.z * c.z + c.w * c.w;
            }
        }

        int tb = g * 32;
        #pragma unroll
        for (int s = 0; s < 8; s++) {
            int t = tb + s * 4;
            float4 qv[4], kv[4];
            #pragma unroll
            for (int r = 0; r < 4; r++) qv[r] = *(const float4*)&qs[(ii0 + r) * PAD + t];
            #pragma unroll
            for (int c = 0; c < 4; c++) kv[c] = *(const float4*)&ks[(jj0 + c) * PAD + t];
            #pragma unroll
            for (int r = 0; r < 4; r++)
                #pragma unroll
                for (int c = 0; c < 4; c++)
                    acc[r][c] += qv[r].x * kv[c].x + qv[r].y * kv[c].y
                               + qv[r].z * kv[c].z + qv[r].w * kv[c].w;
        }
        __syncthreads();
    }

    // reduce norm partials within each 8-lane group, one atomic per row
    #pragma unroll
    for (int o = 4; o > 0; o >>= 1) {
        qacc += __shfl_down_sync(0xffffffffu, qacc, o);
        kacc += __shfl_down_sync(0xffffffffu, kacc, o);
    }
    if ((tid & 7) == 0) {
        atomicAdd(&g_norm2[b * 512 + h * DH + nrow], qacc);
        atomicAdd(&g_norm2[b * 512 + 256 + h * DH + nrow], kacc);
    }

    #pragma unroll
    for (int r = 0; r < 4; r++)
        #pragma unroll
        for (int c = 0; c < 4; c++)
            atomicAdd(&simbuf[(ii0 + r) * 32 + jj0 + c], acc[r][c]);
    __syncthreads();

    float* dst = g_simpart + ((size_t)(z * 128 + bh)) * 1024;
    for (int l = tid; l < 1024; l += 256) dst[l] = simbuf[l];
}

// ---------------- Kernel 6: reduce partials + scales + softmax -> attn ----------------
__global__ void softmax_kernel(const float* __restrict__ temp) {
    __shared__ float kinv[32];
    int bh = blockIdx.x;
    int i = threadIdx.x;
    int b = bh >> 3, h = bh & 7;

    float kn = g_norm2[b * 512 + 256 + h * DH + i];
    kinv[i] = 1.0f / fmaxf(sqrtf(kn), L2_EPS);
    float qn = g_norm2[b * 512 + h * DH + i];
    float qsc = expf(temp[h]) / fmaxf(sqrtf(qn), L2_EPS);
    __syncthreads();

    float row[32];
    float mx = -1e30f;
    #pragma unroll 4
    for (int j = 0; j < 32; j++) {
        float v = 0.f;
        #pragma unroll
        for (int z = 0; z < ZSPLIT; z++)
            v += g_simpart[((size_t)(z * 128 + bh)) * 1024 + i * 32 + j];
        v = v * qsc * kinv[j] * XC_SCALE;
        row[j] = v;
        mx = fmaxf(mx, v);
    }
    float sum = 0.f;
    #pragma unroll
    for (int j = 0; j < 32; j++) { row[j] = expf(row[j] - mx); sum += row[j]; }
    float inv = 1.0f / sum;
    #pragma unroll
    for (int j = 0; j < 32; j++)
        g_attn[((size_t)bh * 32 + i) * 32 + j] = row[j] * inv;
}

// ---------------- Kernel 7: attn @ v, fused transpose + bf16 split ----------------
__global__ __launch_bounds__(256) void av_kernel() {
    __shared__ float at[1024];
    __shared__ float tb[32][257];
    int bh = blockIdx.y;
    int b = bh >> 3, h = bh & 7;
    int tid = threadIdx.x;
    int n = blockIdx.x * 256 + tid;

    for (int l = tid; l < 1024; l += 256) at[l] = g_attn[(size_t)bh * 1024 + l];
    __syncthreads();

    const float* vbase = g_qkv + ((size_t)b * QKV3 + 512 + h * DH) * N_ + n;

    float acc[32] = {};
    #pragma unroll 4
    for (int j = 0; j < 32; j++) {
        float vj = vbase[(size_t)j * N_];
        #pragma unroll
        for (int i = 0; i < 32; i++) acc[i] += at[i * 32 + j] * vj;
    }
    #pragma unroll
    for (int i = 0; i < 32; i++) tb[i][tid] = acc[i];
    __syncthreads();

    unsigned* outh = (unsigned*)g_avhi;
    unsigned* outl = (unsigned*)g_avlo;
    for (int l = tid; l < 4096; l += 256) {
        int nl = l >> 4, u = l & 15;
        float v0 = tb[u * 2 + 0][nl];
        float v1 = tb[u * 2 + 1][nl];
        __nv_bfloat16 h0 = __float2bfloat16(v0);
        __nv_bfloat16 h1 = __float2bfloat16(v1);
        __nv_bfloat16 l0 = __float2bfloat16(v0 - __bfloat162float(h0));
        __nv_bfloat16 l1 = __float2bfloat16(v1 - __bfloat162float(h1));
        int gn = blockIdx.x * 256 + nl;
        size_t idx = ((size_t)(b * 4096 + gn)) * 128 + h * 16 + u;
        outh[idx] = (unsigned)__bfloat16_as_ushort(h0) | ((unsigned)__bfloat16_as_ushort(h1) << 16);
        outl[idx] = (unsigned)__bfloat16_as_ushort(l0) | ((unsigned)__bfloat16_as_ushort(l1) << 16);
    }
}

// ---------------- launch ----------------
extern "C" void kernel_launch(void* const* d_in, const int* in_sizes, int n_in,
                              void* d_out, int out_size) {
    const float* x     = (const float*)d_in[0];
    const float* gamma = (const float*)d_in[1];
    const float* beta  = (const float*)d_in[2];
    const float* Wqkv  = (const float*)d_in[3];
    const float* temp  = (const float*)d_in[4];
    const float* Wout  = (const float*)d_in[5];
    const float* bout  = (const float*)d_in[6];
    float* out = (float*)d_out;
    (void)in_sizes; (void)n_in; (void)out_size;

    cudaFuncSetAttribute(mgemm_kernel, cudaFuncAttributeMaxDynamicSharedMemorySize, 2 * STG);

    zero_kernel<<<32, 256>>>();
    lnconv_kernel<<<dim3(N_ / 32, B_), 256>>>(x, gamma, beta);
    wsplit_kernel<<<256, dim3(32, 8)>>>(Wqkv, Wout);
    // QKV projection (2-stage pipelined HMMA, R5-exact)
    mgemm_kernel<<<dim3(N_ / 128, QKV3 / 128, B_), 256, 2 * STG>>>(0, nullptr, nullptr, QKV3);
    // sim partials + fused norms, then softmax (scales finalized inside)
    sim_part_kernel<<<dim3(B_ * HEADS, ZSPLIT), 256>>>();
    softmax_kernel<<<B_ * HEADS, 32>>>(temp);
    // attn @ v
    av_kernel<<<dim3(N_ / 256, B_ * HEADS), 256>>>();
    // output projection + bias -> d_out
    mgemm_kernel<<<dim3(N_ / 128, C_ / 128, B_), 256, 2 * STG>>>(1, out, bout, C_);
}